// round 1
// baseline (speedup 1.0000x reference)
#include <cuda_runtime.h>
#include <math.h>

#define BB   4
#define SS   1024
#define HH   16
#define SZ   64
#define DIMM 1024
#define NINF -10000.0f

// ---------------- scratch (device globals; no runtime allocation) ----------
__device__ float g_q[BB * SS * DIMM];
__device__ float g_k[BB * SS * DIMM];
__device__ float g_v[BB * SS * DIMM];
__device__ float g_ctx[BB * SS * DIMM];
__device__ float g_res[BB * SS * DIMM];
__device__ float g_attn_scratch[BB * HH * SS * SS]; // fallback if d_out has no room

// ---------------------------------------------------------------------------
// 128x128x8 fp32 SGEMM, 256 threads, 8x8 per thread.
// C = A[M,K] @ W[K,N] + bias[N] (+ resid[M,N] if non-null)
// ---------------------------------------------------------------------------
__global__ __launch_bounds__(256) void sgemm128(
    const float* __restrict__ A, const float* __restrict__ W,
    const float* __restrict__ bias, const float* __restrict__ resid,
    float* __restrict__ C, int M, int N, int K)
{
    __shared__ float As[8][132];   // A tile transposed: As[k][m], pad kills store conflicts
    __shared__ float Ws[8][128];   // W tile: Ws[k][n]

    const int tid = threadIdx.x;
    const int bm = blockIdx.y * 128;
    const int bn = blockIdx.x * 128;

    const int rowBase = (tid / 16) * 8;   // 0..120
    const int colBase = (tid % 16) * 8;   // 0..120

    const int aRow = tid >> 1;            // 0..127
    const int aCol = (tid & 1) * 4;       // 0 or 4
    const int wRow = tid >> 5;            // 0..7
    const int wCol = (tid & 31) * 4;      // 0..124

    const float* Ap = A + (size_t)(bm + aRow) * K + aCol;
    const float* Wp = W + (size_t)wRow * N + bn + wCol;

    float acc[8][8];
#pragma unroll
    for (int i = 0; i < 8; i++)
#pragma unroll
        for (int j = 0; j < 8; j++) acc[i][j] = 0.f;

    for (int kt = 0; kt < K; kt += 8) {
        float4 av = *(const float4*)(Ap + kt);
        float4 wv = *(const float4*)(Wp + (size_t)kt * N);
        As[aCol + 0][aRow] = av.x;
        As[aCol + 1][aRow] = av.y;
        As[aCol + 2][aRow] = av.z;
        As[aCol + 3][aRow] = av.w;
        *(float4*)&Ws[wRow][wCol] = wv;
        __syncthreads();

#pragma unroll
        for (int kk = 0; kk < 8; kk++) {
            float a[8], b[8];
            *(float4*)&a[0] = *(const float4*)&As[kk][rowBase];
            *(float4*)&a[4] = *(const float4*)&As[kk][rowBase + 4];
            *(float4*)&b[0] = *(const float4*)&Ws[kk][colBase];
            *(float4*)&b[4] = *(const float4*)&Ws[kk][colBase + 4];
#pragma unroll
            for (int i = 0; i < 8; i++)
#pragma unroll
                for (int j = 0; j < 8; j++)
                    acc[i][j] += a[i] * b[j];
        }
        __syncthreads();
    }

#pragma unroll
    for (int i = 0; i < 8; i++) {
        const int row = bm + rowBase + i;
        float* Crow = C + (size_t)row * N + bn + colBase;
        const float* Rrow = resid ? (resid + (size_t)row * N + bn + colBase) : nullptr;
#pragma unroll
        for (int j = 0; j < 8; j++) {
            float val = acc[i][j] + bias[bn + colBase + j];
            if (Rrow) val += Rrow[j];
            Crow[j] = val;
        }
    }
}

// ---------------------------------------------------------------------------
// Fused attention: one block = (b, h, 16 query rows). 256 threads.
// scores[16][1024] held entirely in smem; softmax exact-same math as reference.
// Writes attn [B,H,S,S] and ctx in [B,S,DIM] layout.
// ---------------------------------------------------------------------------
#define TS 16
#define QT_STR 20     // sQt[d][i], stride 20 -> 16B-aligned float4 reads
#define KT_STR 65     // sKt[d][j], stride 65 -> conflict-free column reads
#define V_STR  68     // sV[j][d], stride 68 -> aligned float4 reads
#define S_STR  1040   // sS[i][t], stride 1040 -> bank-shifted rows

#define ATTN_SMEM_FLOATS (64 * QT_STR + 64 * V_STR + TS * S_STR + 32)

__global__ __launch_bounds__(256) void attn_kernel(
    const float* __restrict__ q, const float* __restrict__ k,
    const float* __restrict__ v, const float* __restrict__ rel,
    const int* __restrict__ mask, float* __restrict__ attn_out,
    float* __restrict__ ctx)
{
    extern __shared__ float sm[];
    float* sQt  = sm;                       // [64][QT_STR]
    float* sKV  = sQt + 64 * QT_STR;        // K transposed [64][65] or V [64][68]
    float* sS   = sKV + 64 * V_STR;         // [16][S_STR]
    float* sMax = sS + TS * S_STR;          // [16]
    float* sSum = sMax + 16;                // [16]

    const int tid = threadIdx.x;
    const int b = blockIdx.z, h = blockIdx.y;
    const int sb = blockIdx.x * TS;

    const float* qb = q + ((size_t)b * SS + sb) * DIMM + h * SZ;
    const float* kb = k + (size_t)b * SS * DIMM + h * SZ;
    const float* vb = v + (size_t)b * SS * DIMM + h * SZ;
    const float* relb = rel + ((size_t)h * SS + sb) * SS;
    const int* maskb = mask + b * SS;

    // ---- load Q tile, transposed + pre-scaled by 1/sqrt(64) ----
    for (int idx = tid; idx < TS * SZ; idx += 256) {
        const int i = idx >> 6, d = idx & 63;
        sQt[d * QT_STR + i] = qb[(size_t)i * DIMM + d] * 0.125f;
    }

    // ---- scores: thread handles column j, rows i0..i0+3 ----
    {
        const int j  = tid & 63;
        const int i0 = (tid >> 6) * 4;
        for (int tt = 0; tt < SS; tt += 64) {
            // load K tile transposed: sKt[d][r]
            for (int idx = tid; idx < 64 * 64; idx += 256) {
                const int r = idx >> 6, c = idx & 63;
                sKV[c * KT_STR + r] = kb[(size_t)(tt + r) * DIMM + c];
            }
            __syncthreads();

            float a0 = 0.f, a1 = 0.f, a2 = 0.f, a3 = 0.f;
#pragma unroll 16
            for (int d = 0; d < 64; d++) {
                const float kv = sKV[d * KT_STR + j];
                const float4 qv = *(const float4*)&sQt[d * QT_STR + i0];
                a0 += qv.x * kv;
                a1 += qv.y * kv;
                a2 += qv.z * kv;
                a3 += qv.w * kv;
            }
            const int t = tt + j;
            const float mterm = (float)maskb[t] * NINF;
            sS[(i0 + 0) * S_STR + t] = a0 + relb[(size_t)(i0 + 0) * SS + t] + mterm;
            sS[(i0 + 1) * S_STR + t] = a1 + relb[(size_t)(i0 + 1) * SS + t] + mterm;
            sS[(i0 + 2) * S_STR + t] = a2 + relb[(size_t)(i0 + 2) * SS + t] + mterm;
            sS[(i0 + 3) * S_STR + t] = a3 + relb[(size_t)(i0 + 3) * SS + t] + mterm;
            __syncthreads();
        }
    }

    // ---- softmax reductions: 16 threads per row ----
    {
        const int r = tid >> 4;
        const int l = tid & 15;
        float mx = -1e30f;
        for (int t = l; t < SS; t += 16) mx = fmaxf(mx, sS[r * S_STR + t]);
#pragma unroll
        for (int o = 8; o >= 1; o >>= 1) mx = fmaxf(mx, __shfl_xor_sync(~0u, mx, o));
        if (l == 0) sMax[r] = mx;
        __syncthreads();
        const float rowmax = sMax[r];
        float sum = 0.f;
        for (int t = l; t < SS; t += 16) sum += __expf(sS[r * S_STR + t] - rowmax);
#pragma unroll
        for (int o = 8; o >= 1; o >>= 1) sum += __shfl_xor_sync(~0u, sum, o);
        if (l == 0) sSum[r] = sum;
        __syncthreads();
        if (tid < TS) sSum[tid] = 1.f / sSum[tid];
        __syncthreads();
    }

    // ---- normalize, write attn (coalesced), keep p in sS ----
    {
        float* attnb = attn_out + (((size_t)b * HH + h) * SS + sb) * SS;
        for (int idx = tid; idx < TS * SS; idx += 256) {
            const int i = idx >> 10, t = idx & 1023;
            const float p = __expf(sS[i * S_STR + t] - sMax[i]) * sSum[i];
            sS[i * S_STR + t] = p;
            attnb[(size_t)i * SS + t] = p;
        }
        __syncthreads();
    }

    // ---- ctx = p @ V : thread handles row i, dims d0..d0+3 ----
    {
        const int i  = tid >> 4;
        const int d0 = (tid & 15) * 4;
        float c0 = 0.f, c1 = 0.f, c2 = 0.f, c3 = 0.f;
        for (int tt = 0; tt < SS; tt += 64) {
            for (int idx = tid; idx < 64 * 64; idx += 256) {
                const int r = idx >> 6, c = idx & 63;
                sKV[r * V_STR + c] = vb[(size_t)(tt + r) * DIMM + c];
            }
            __syncthreads();
#pragma unroll 16
            for (int jj = 0; jj < 64; jj++) {
                const float p = sS[i * S_STR + tt + jj];
                const float4 vv = *(const float4*)&sKV[jj * V_STR + d0];
                c0 += p * vv.x;
                c1 += p * vv.y;
                c2 += p * vv.z;
                c3 += p * vv.w;
            }
            __syncthreads();
        }
        float* cp = ctx + ((size_t)b * SS + sb + i) * DIMM + h * SZ + d0;
        float4 o4 = make_float4(c0, c1, c2, c3);
        *(float4*)cp = o4;
    }
}

// ---------------------------------------------------------------------------
// LayerNorm: one block per row (1024 elems, 256 threads x float4)
// ---------------------------------------------------------------------------
__global__ __launch_bounds__(256) void ln_kernel(
    const float* __restrict__ res, const float* __restrict__ gamma,
    const float* __restrict__ beta, float* __restrict__ out)
{
    __shared__ float sred[2][8];
    const int row = blockIdx.x;
    const int tid = threadIdx.x;
    const float4 vv = ((const float4*)(res + (size_t)row * DIMM))[tid];
    float s  = vv.x + vv.y + vv.z + vv.w;
    float ss = vv.x * vv.x + vv.y * vv.y + vv.z * vv.z + vv.w * vv.w;
#pragma unroll
    for (int o = 16; o >= 1; o >>= 1) {
        s  += __shfl_xor_sync(~0u, s, o);
        ss += __shfl_xor_sync(~0u, ss, o);
    }
    if ((tid & 31) == 0) { sred[0][tid >> 5] = s; sred[1][tid >> 5] = ss; }
    __syncthreads();
    float ts = 0.f, tss = 0.f;
#pragma unroll
    for (int i = 0; i < 8; i++) { ts += sred[0][i]; tss += sred[1][i]; }
    const float mu   = ts * (1.f / DIMM);
    const float var  = tss * (1.f / DIMM) - mu * mu;
    const float rstd = rsqrtf(var + 1e-6f);
    const float4 g  = ((const float4*)gamma)[tid];
    const float4 be = ((const float4*)beta)[tid];
    float4 o4;
    o4.x = (vv.x - mu) * rstd * g.x + be.x;
    o4.y = (vv.y - mu) * rstd * g.y + be.y;
    o4.z = (vv.z - mu) * rstd * g.z + be.z;
    o4.w = (vv.w - mu) * rstd * g.w + be.w;
    ((float4*)(out + (size_t)row * DIMM))[tid] = o4;
}

// ---------------------------------------------------------------------------
extern "C" void kernel_launch(void* const* d_in, const int* in_sizes, int n_in,
                              void* d_out, int out_size)
{
    const float* x     = (const float*)d_in[0];
    const int*   mask  = (const int*)d_in[1];
    const float* rel   = (const float*)d_in[2];
    const float* Wq    = (const float*)d_in[3];
    const float* bq    = (const float*)d_in[4];
    const float* Wk    = (const float*)d_in[5];
    const float* bk    = (const float*)d_in[6];
    const float* Wv    = (const float*)d_in[7];
    const float* bv    = (const float*)d_in[8];
    const float* Wo    = (const float*)d_in[9];
    const float* bo    = (const float*)d_in[10];
    const float* gamma = (const float*)d_in[11];
    const float* beta  = (const float*)d_in[12];
    float* out = (float*)d_out;

    float *q, *k, *v, *ctx, *res, *attn_scr;
    cudaGetSymbolAddress((void**)&q,        g_q);
    cudaGetSymbolAddress((void**)&k,        g_k);
    cudaGetSymbolAddress((void**)&v,        g_v);
    cudaGetSymbolAddress((void**)&ctx,      g_ctx);
    cudaGetSymbolAddress((void**)&res,      g_res);
    cudaGetSymbolAddress((void**)&attn_scr, g_attn_scratch);

    const size_t OUT_E  = (size_t)BB * SS * DIMM;            // 4M
    const size_t ATTN_E = (size_t)BB * HH * SS * SS;         // 64M
    float* attn_out = ((size_t)out_size >= OUT_E + ATTN_E) ? (out + OUT_E)
                                                           : attn_scr;

    const int M = BB * SS;  // 4096
    dim3 gg(DIMM / 128, M / 128);   // (8, 32)

    sgemm128<<<gg, 256>>>(x, Wq, bq, nullptr, q, M, DIMM, DIMM);
    sgemm128<<<gg, 256>>>(x, Wk, bk, nullptr, k, M, DIMM, DIMM);
    sgemm128<<<gg, 256>>>(x, Wv, bv, nullptr, v, M, DIMM, DIMM);

    const int smem = ATTN_SMEM_FLOATS * (int)sizeof(float);  // 89216 B
    cudaFuncSetAttribute(attn_kernel,
                         cudaFuncAttributeMaxDynamicSharedMemorySize, smem);
    attn_kernel<<<dim3(SS / TS, HH, BB), 256, smem>>>(q, k, v, rel, mask,
                                                      attn_out, ctx);

    sgemm128<<<gg, 256>>>(ctx, Wo, bo, x, res, M, DIMM, DIMM);
    ln_kernel<<<M, 256>>>(res, gamma, beta, out);
}

// round 2
// speedup vs baseline: 2.5548x; 2.5548x over previous
#include <cuda_runtime.h>
#include <math.h>
#include <stdint.h>

#define BB   4
#define SS   1024
#define HH   16
#define SZ   64
#define DIMM 1024
#define NINF -10000.0f

// ---------------- scratch (device globals; no runtime allocation) ----------
__device__ float g_q[BB * SS * DIMM];
__device__ float g_k[BB * SS * DIMM];
__device__ float g_v[BB * SS * DIMM];
__device__ float g_ctx[BB * SS * DIMM];
__device__ float g_res[BB * SS * DIMM];
__device__ float g_attn_scratch[BB * HH * SS * SS];

// ---------------- small PTX helpers ----------------------------------------
__device__ __forceinline__ uint32_t f2tf(float f) {
    uint32_t r;
    asm volatile("cvt.rna.tf32.f32 %0, %1;" : "=r"(r) : "f"(f));
    return r;
}
__device__ __forceinline__ void mma_tf32(float c[4], const uint32_t a[4],
                                         const uint32_t b[2]) {
    asm volatile(
        "mma.sync.aligned.m16n8k8.row.col.f32.tf32.tf32.f32 "
        "{%0,%1,%2,%3}, {%4,%5,%6,%7}, {%8,%9}, {%0,%1,%2,%3};"
        : "+f"(c[0]), "+f"(c[1]), "+f"(c[2]), "+f"(c[3])
        : "r"(a[0]), "r"(a[1]), "r"(a[2]), "r"(a[3]), "r"(b[0]), "r"(b[1]));
}
__device__ __forceinline__ void cp16(uint32_t s, const void* g) {
    asm volatile("cp.async.cg.shared.global [%0], [%1], 16;" :: "r"(s), "l"(g));
}
#define CP_COMMIT() asm volatile("cp.async.commit_group;")
#define CP_WAIT1()  asm volatile("cp.async.wait_group 1;")
#define CP_WAIT0()  asm volatile("cp.async.wait_group 0;")

// ---------------------------------------------------------------------------
// TF32 GEMM: C[M,N] = A[M,K] @ W[K,N] + bias (+ resid). 128x128x32 tiles.
// 256 threads = 8 warps (2 x 4), each warp 64x32 via m16n8k8.
// ---------------------------------------------------------------------------
#define A_STR 36
#define W_STR 136
#define A_TILE (128 * A_STR)   // 4608 floats
#define W_TILE (32 * W_STR)    // 4352 floats
#define GEMM_SMEM ((A_TILE + W_TILE) * 2 * 4)  // 71680 bytes

__global__ __launch_bounds__(256, 2) void gemm_tf32(
    const float* __restrict__ A, const float* __restrict__ W,
    const float* __restrict__ bias, const float* __restrict__ resid,
    float* __restrict__ C, int M, int N, int K)
{
    extern __shared__ float sm[];
    float* As[2] = { sm, sm + A_TILE + W_TILE };
    float* Ws[2] = { sm + A_TILE, sm + A_TILE + W_TILE + A_TILE };

    const int tid  = threadIdx.x;
    const int lane = tid & 31;
    const int warp = tid >> 5;
    const int wm = warp >> 2;       // 0..1 -> 64 rows
    const int wn = warp & 3;        // 0..3 -> 32 cols
    const int r = lane >> 2;        // 0..7
    const int cl = lane & 3;        // 0..3

    const int bm = blockIdx.y * 128;
    const int bn = blockIdx.x * 128;

    float acc[4][4][4];
#pragma unroll
    for (int mt = 0; mt < 4; mt++)
#pragma unroll
        for (int nt = 0; nt < 4; nt++)
#pragma unroll
            for (int i = 0; i < 4; i++) acc[mt][nt][i] = 0.f;

    // copy one k-chunk (A 128x32, W 32x128) into buffer `b`
    auto load_stage = [&](int b, int kt) {
        float* as = As[b];
        float* ws = Ws[b];
#pragma unroll
        for (int j = 0; j < 4; j++) {
            const int idx = tid + j * 256;            // 0..1023 float4s
            const int ar = idx >> 3, ac = (idx & 7) * 4;
            cp16((uint32_t)__cvta_generic_to_shared(as + ar * A_STR + ac),
                 A + (size_t)(bm + ar) * K + kt + ac);
            const int wk = idx >> 5, wc = (idx & 31) * 4;
            cp16((uint32_t)__cvta_generic_to_shared(ws + wk * W_STR + wc),
                 W + (size_t)(kt + wk) * N + bn + wc);
        }
    };

    load_stage(0, 0);
    CP_COMMIT();

    const int T = K / 32;
    int buf = 0;
    for (int t = 0; t < T; t++) {
        if (t + 1 < T) { load_stage(buf ^ 1, (t + 1) * 32); CP_COMMIT(); CP_WAIT1(); }
        else           { CP_WAIT0(); }
        __syncthreads();

        const float* as = As[buf];
        const float* ws = Ws[buf];
#pragma unroll
        for (int ks = 0; ks < 4; ks++) {
            uint32_t af[4][4];
#pragma unroll
            for (int mt = 0; mt < 4; mt++) {
                const float* p = as + (wm * 64 + mt * 16 + r) * A_STR + ks * 8 + cl;
                af[mt][0] = f2tf(p[0]);
                af[mt][1] = f2tf(p[8 * A_STR]);
                af[mt][2] = f2tf(p[4]);
                af[mt][3] = f2tf(p[8 * A_STR + 4]);
            }
            uint32_t bf[4][2];
#pragma unroll
            for (int nt = 0; nt < 4; nt++) {
                const float* p = ws + (ks * 8 + cl) * W_STR + wn * 32 + nt * 8 + r;
                bf[nt][0] = f2tf(p[0]);
                bf[nt][1] = f2tf(p[4 * W_STR]);
            }
#pragma unroll
            for (int mt = 0; mt < 4; mt++)
#pragma unroll
                for (int nt = 0; nt < 4; nt++)
                    mma_tf32(acc[mt][nt], af[mt], bf[nt]);
        }
        __syncthreads();
        buf ^= 1;
    }

    // epilogue
#pragma unroll
    for (int mt = 0; mt < 4; mt++) {
        const int row0 = bm + wm * 64 + mt * 16 + r;
#pragma unroll
        for (int nt = 0; nt < 4; nt++) {
            const int col = bn + wn * 32 + nt * 8 + 2 * cl;
            const float b0 = bias[col], b1 = bias[col + 1];
            float v00 = acc[mt][nt][0] + b0, v01 = acc[mt][nt][1] + b1;
            float v10 = acc[mt][nt][2] + b0, v11 = acc[mt][nt][3] + b1;
            if (resid) {
                v00 += resid[(size_t)row0 * N + col];
                v01 += resid[(size_t)row0 * N + col + 1];
                v10 += resid[(size_t)(row0 + 8) * N + col];
                v11 += resid[(size_t)(row0 + 8) * N + col + 1];
            }
            *(float2*)(C + (size_t)row0 * N + col)       = make_float2(v00, v01);
            *(float2*)(C + (size_t)(row0 + 8) * N + col) = make_float2(v10, v11);
        }
    }
}

// ---------------------------------------------------------------------------
// Fused attention with TF32 mma. Block = (b, h, 16 queries). 256 thr / 8 warps.
// ---------------------------------------------------------------------------
#define TS 16
#define Q_STR 68
#define KV_STR 68
#define S_STR 1044
#define ATTN_SMEM_FLOATS (TS * Q_STR + 128 * KV_STR + TS * S_STR + 32)

__global__ __launch_bounds__(256) void attn_kernel(
    const float* __restrict__ q, const float* __restrict__ k,
    const float* __restrict__ v, const float* __restrict__ rel,
    const int* __restrict__ mask, float* __restrict__ attn_out,
    float* __restrict__ ctx)
{
    extern __shared__ float sm[];
    float* sQ   = sm;                         // [16][Q_STR]
    float* sKV  = sQ + TS * Q_STR;            // [128][KV_STR]
    float* sS   = sKV + 128 * KV_STR;         // [16][S_STR]
    float* sMax = sS + TS * S_STR;            // [16]
    float* sSum = sMax + 16;                  // [16]

    const int tid  = threadIdx.x;
    const int lane = tid & 31;
    const int w    = tid >> 5;
    const int r    = lane >> 2;   // 0..7
    const int cl   = lane & 3;    // 0..3

    const int b = blockIdx.z, h = blockIdx.y;
    const int sb = blockIdx.x * TS;

    const float* qb = q + ((size_t)b * SS + sb) * DIMM + h * SZ;
    const float* kb = k + (size_t)b * SS * DIMM + h * SZ;
    const float* vb = v + (size_t)b * SS * DIMM + h * SZ;
    const float* relb = rel + ((size_t)h * SS + sb) * SS;
    const int* maskb = mask + b * SS;

    // ---- load Q (prescaled by 1/8) ----
    for (int idx = tid; idx < TS * SZ; idx += 256) {
        const int i = idx >> 6, d = idx & 63;
        sQ[i * Q_STR + d] = qb[(size_t)i * DIMM + d] * 0.125f;
    }

    // ---- scores: loop key blocks of 128; each warp takes 16 keys ----
    for (int kblk = 0; kblk < 8; kblk++) {
        __syncthreads();
        // stage K block
        for (int idx = tid; idx < 128 * 16; idx += 256) {
            const int kr = idx >> 4, c4 = (idx & 15) * 4;
            *(float4*)&sKV[kr * KV_STR + c4] =
                *(const float4*)(kb + (size_t)(kblk * 128 + kr) * DIMM + c4);
        }
        __syncthreads();

        float acc[2][4] = {{0.f,0.f,0.f,0.f},{0.f,0.f,0.f,0.f}};
#pragma unroll
        for (int ks = 0; ks < 8; ks++) {
            uint32_t af[4];
            const float* ap = sQ + r * Q_STR + ks * 8 + cl;
            af[0] = f2tf(ap[0]);
            af[1] = f2tf(ap[8 * Q_STR]);
            af[2] = f2tf(ap[4]);
            af[3] = f2tf(ap[8 * Q_STR + 4]);
#pragma unroll
            for (int nt = 0; nt < 2; nt++) {
                uint32_t bf[2];
                const float* bp = sKV + (w * 16 + nt * 8 + r) * KV_STR + ks * 8 + cl;
                bf[0] = f2tf(bp[0]);
                bf[1] = f2tf(bp[4]);
                mma_tf32(acc[nt], af, bf);
            }
        }
        // write scores with rel + mask
#pragma unroll
        for (int nt = 0; nt < 2; nt++) {
            const int t = kblk * 128 + w * 16 + nt * 8 + 2 * cl;
            const float m0 = (float)maskb[t] * NINF;
            const float m1 = (float)maskb[t + 1] * NINF;
            sS[r * S_STR + t]           = acc[nt][0] + relb[(size_t)r * SS + t] + m0;
            sS[r * S_STR + t + 1]       = acc[nt][1] + relb[(size_t)r * SS + t + 1] + m1;
            sS[(r + 8) * S_STR + t]     = acc[nt][2] + relb[(size_t)(r + 8) * SS + t] + m0;
            sS[(r + 8) * S_STR + t + 1] = acc[nt][3] + relb[(size_t)(r + 8) * SS + t + 1] + m1;
        }
    }
    __syncthreads();

    // ---- softmax reductions: 16 threads per row ----
    {
        const int row = tid >> 4;
        const int l = tid & 15;
        float mx = -1e30f;
        for (int t = l; t < SS; t += 16) mx = fmaxf(mx, sS[row * S_STR + t]);
#pragma unroll
        for (int o = 8; o >= 1; o >>= 1) mx = fmaxf(mx, __shfl_xor_sync(~0u, mx, o));
        if (l == 0) sMax[row] = mx;
        __syncthreads();
        const float rowmax = sMax[row];
        float sum = 0.f;
        for (int t = l; t < SS; t += 16) sum += __expf(sS[row * S_STR + t] - rowmax);
#pragma unroll
        for (int o = 8; o >= 1; o >>= 1) sum += __shfl_xor_sync(~0u, sum, o);
        if (l == 0) sSum[row] = sum;
        __syncthreads();
        if (tid < TS) sSum[tid] = 1.f / sSum[tid];
        __syncthreads();
    }

    // ---- normalize, write attn, keep p in sS ----
    {
        float* attnb = attn_out + (((size_t)b * HH + h) * SS + sb) * SS;
        for (int idx = tid; idx < TS * SS; idx += 256) {
            const int i = idx >> 10, t = idx & 1023;
            const float p = __expf(sS[i * S_STR + t] - sMax[i]) * sSum[i];
            sS[i * S_STR + t] = p;
            attnb[(size_t)i * SS + t] = p;
        }
    }

    // ---- ctx = P @ V : warp w owns dims [w*8, w*8+8), all 16 rows ----
    {
        float acc[4] = {0.f, 0.f, 0.f, 0.f};
        for (int kblk = 0; kblk < 8; kblk++) {
            __syncthreads();
            for (int idx = tid; idx < 128 * 16; idx += 256) {
                const int kr = idx >> 4, c4 = (idx & 15) * 4;
                *(float4*)&sKV[kr * KV_STR + c4] =
                    *(const float4*)(vb + (size_t)(kblk * 128 + kr) * DIMM + c4);
            }
            __syncthreads();
#pragma unroll
            for (int ks = 0; ks < 16; ks++) {
                uint32_t af[4];
                const float* ap = sS + r * S_STR + kblk * 128 + ks * 8 + cl;
                af[0] = f2tf(ap[0]);
                af[1] = f2tf(ap[8 * S_STR]);
                af[2] = f2tf(ap[4]);
                af[3] = f2tf(ap[8 * S_STR + 4]);
                uint32_t bf[2];
                const float* bp = sKV + (ks * 8 + cl) * KV_STR + w * 8 + r;
                bf[0] = f2tf(bp[0]);
                bf[1] = f2tf(bp[4 * KV_STR]);
                mma_tf32(acc, af, bf);
            }
        }
        float* cp0 = ctx + ((size_t)b * SS + sb + r) * DIMM + h * SZ + w * 8 + 2 * cl;
        float* cp1 = ctx + ((size_t)b * SS + sb + r + 8) * DIMM + h * SZ + w * 8 + 2 * cl;
        *(float2*)cp0 = make_float2(acc[0], acc[1]);
        *(float2*)cp1 = make_float2(acc[2], acc[3]);
    }
}

// ---------------------------------------------------------------------------
// LayerNorm: one block per row
// ---------------------------------------------------------------------------
__global__ __launch_bounds__(256) void ln_kernel(
    const float* __restrict__ res, const float* __restrict__ gamma,
    const float* __restrict__ beta, float* __restrict__ out)
{
    __shared__ float sred[2][8];
    const int row = blockIdx.x;
    const int tid = threadIdx.x;
    const float4 vv = ((const float4*)(res + (size_t)row * DIMM))[tid];
    float s  = vv.x + vv.y + vv.z + vv.w;
    float ss = vv.x * vv.x + vv.y * vv.y + vv.z * vv.z + vv.w * vv.w;
#pragma unroll
    for (int o = 16; o >= 1; o >>= 1) {
        s  += __shfl_xor_sync(~0u, s, o);
        ss += __shfl_xor_sync(~0u, ss, o);
    }
    if ((tid & 31) == 0) { sred[0][tid >> 5] = s; sred[1][tid >> 5] = ss; }
    __syncthreads();
    float ts = 0.f, tss = 0.f;
#pragma unroll
    for (int i = 0; i < 8; i++) { ts += sred[0][i]; tss += sred[1][i]; }
    const float mu   = ts * (1.f / DIMM);
    const float var  = tss * (1.f / DIMM) - mu * mu;
    const float rstd = rsqrtf(var + 1e-6f);
    const float4 g  = ((const float4*)gamma)[tid];
    const float4 be = ((const float4*)beta)[tid];
    float4 o4;
    o4.x = (vv.x - mu) * rstd * g.x + be.x;
    o4.y = (vv.y - mu) * rstd * g.y + be.y;
    o4.z = (vv.z - mu) * rstd * g.z + be.z;
    o4.w = (vv.w - mu) * rstd * g.w + be.w;
    ((float4*)(out + (size_t)row * DIMM))[tid] = o4;
}

// ---------------------------------------------------------------------------
extern "C" void kernel_launch(void* const* d_in, const int* in_sizes, int n_in,
                              void* d_out, int out_size)
{
    const float* x     = (const float*)d_in[0];
    const int*   mask  = (const int*)d_in[1];
    const float* rel   = (const float*)d_in[2];
    const float* Wq    = (const float*)d_in[3];
    const float* bq    = (const float*)d_in[4];
    const float* Wk    = (const float*)d_in[5];
    const float* bk    = (const float*)d_in[6];
    const float* Wv    = (const float*)d_in[7];
    const float* bv    = (const float*)d_in[8];
    const float* Wo    = (const float*)d_in[9];
    const float* bo    = (const float*)d_in[10];
    const float* gamma = (const float*)d_in[11];
    const float* beta  = (const float*)d_in[12];
    float* out = (float*)d_out;

    float *q, *k, *v, *ctx, *res, *attn_scr;
    cudaGetSymbolAddress((void**)&q,        g_q);
    cudaGetSymbolAddress((void**)&k,        g_k);
    cudaGetSymbolAddress((void**)&v,        g_v);
    cudaGetSymbolAddress((void**)&ctx,      g_ctx);
    cudaGetSymbolAddress((void**)&res,      g_res);
    cudaGetSymbolAddress((void**)&attn_scr, g_attn_scratch);

    const size_t OUT_E  = (size_t)BB * SS * DIMM;
    const size_t ATTN_E = (size_t)BB * HH * SS * SS;
    float* attn_out = ((size_t)out_size >= OUT_E + ATTN_E) ? (out + OUT_E)
                                                           : attn_scr;

    const int M = BB * SS;  // 4096
    dim3 gg(DIMM / 128, M / 128);

    cudaFuncSetAttribute(gemm_tf32,
                         cudaFuncAttributeMaxDynamicSharedMemorySize, GEMM_SMEM);
    gemm_tf32<<<gg, 256, GEMM_SMEM>>>(x, Wq, bq, nullptr, q, M, DIMM, DIMM);
    gemm_tf32<<<gg, 256, GEMM_SMEM>>>(x, Wk, bk, nullptr, k, M, DIMM, DIMM);
    gemm_tf32<<<gg, 256, GEMM_SMEM>>>(x, Wv, bv, nullptr, v, M, DIMM, DIMM);

    const int smem = ATTN_SMEM_FLOATS * (int)sizeof(float);
    cudaFuncSetAttribute(attn_kernel,
                         cudaFuncAttributeMaxDynamicSharedMemorySize, smem);
    attn_kernel<<<dim3(SS / TS, HH, BB), 256, smem>>>(q, k, v, rel, mask,
                                                      attn_out, ctx);

    gemm_tf32<<<gg, 256, GEMM_SMEM>>>(ctx, Wo, bo, x, res, M, DIMM, DIMM);
    ln_kernel<<<M, 256>>>(res, gamma, beta, out);
}

// round 4
// speedup vs baseline: 4.1990x; 1.6436x over previous
#include <cuda_runtime.h>
#include <math.h>
#include <stdint.h>

#define BB   4
#define SS   1024
#define HH   16
#define SZ   64
#define DIMM 1024
#define NINF -10000.0f

// ---------------- scratch (device globals; no runtime allocation) ----------
__device__ float g_q[BB * SS * DIMM];
__device__ float g_k[BB * SS * DIMM];
__device__ float g_v[BB * SS * DIMM];
__device__ float g_ctx[BB * SS * DIMM];
__device__ float g_res[BB * SS * DIMM];
__device__ float g_attn_scratch[BB * HH * SS * SS];

// ---------------- small PTX helpers ----------------------------------------
__device__ __forceinline__ uint32_t f2tf(float f) {
    uint32_t r;
    asm volatile("cvt.rna.tf32.f32 %0, %1;" : "=r"(r) : "f"(f));
    return r;
}
__device__ __forceinline__ void mma_tf32(float c[4], const uint32_t a[4],
                                         const uint32_t b[2]) {
    asm volatile(
        "mma.sync.aligned.m16n8k8.row.col.f32.tf32.tf32.f32 "
        "{%0,%1,%2,%3}, {%4,%5,%6,%7}, {%8,%9}, {%0,%1,%2,%3};"
        : "+f"(c[0]), "+f"(c[1]), "+f"(c[2]), "+f"(c[3])
        : "r"(a[0]), "r"(a[1]), "r"(a[2]), "r"(a[3]), "r"(b[0]), "r"(b[1]));
}
__device__ __forceinline__ void cp16(uint32_t s, const void* g) {
    asm volatile("cp.async.cg.shared.global [%0], [%1], 16;" :: "r"(s), "l"(g));
}
#define CP_COMMIT() asm volatile("cp.async.commit_group;")
#define CP_WAIT1()  asm volatile("cp.async.wait_group 1;")
#define CP_WAIT0()  asm volatile("cp.async.wait_group 0;")

// ---------------------------------------------------------------------------
// TF32 GEMM core: 128x128x32 tiles, 256 threads, 8 warps (2x4), 64x32 / warp
// ---------------------------------------------------------------------------
#define A_STR 36
#define W_STR 136
#define A_TILE (128 * A_STR)
#define W_TILE (32 * W_STR)
#define GEMM_SMEM ((A_TILE + W_TILE) * 2 * 4)  // 71680 B

struct GemmCore {
    const float* A; const float* W; int N; int K; int bm; int bn;
    float* smem;
    float acc[4][4][4];

    __device__ __forceinline__ void run(int tid) {
        float* As[2] = { smem, smem + A_TILE + W_TILE };
        float* Ws[2] = { smem + A_TILE, smem + A_TILE + W_TILE + A_TILE };
        const int lane = tid & 31, warp = tid >> 5;
        const int wm = warp >> 2, wn = warp & 3;
        const int r = lane >> 2, cl = lane & 3;

#pragma unroll
        for (int mt = 0; mt < 4; mt++)
#pragma unroll
            for (int nt = 0; nt < 4; nt++)
#pragma unroll
                for (int i = 0; i < 4; i++) acc[mt][nt][i] = 0.f;

        auto load_stage = [&](int b, int kt) {
            float* as = As[b];
            float* ws = Ws[b];
#pragma unroll
            for (int j = 0; j < 4; j++) {
                const int idx = tid + j * 256;
                const int ar = idx >> 3, ac = (idx & 7) * 4;
                cp16((uint32_t)__cvta_generic_to_shared(as + ar * A_STR + ac),
                     A + (size_t)(bm + ar) * K + kt + ac);
                const int wk = idx >> 5, wc = (idx & 31) * 4;
                cp16((uint32_t)__cvta_generic_to_shared(ws + wk * W_STR + wc),
                     W + (size_t)(kt + wk) * N + bn + wc);
            }
        };

        load_stage(0, 0);
        CP_COMMIT();

        const int T = K / 32;
        int buf = 0;
        for (int t = 0; t < T; t++) {
            if (t + 1 < T) { load_stage(buf ^ 1, (t + 1) * 32); CP_COMMIT(); CP_WAIT1(); }
            else           { CP_WAIT0(); }
            __syncthreads();
            const float* as = As[buf];
            const float* ws = Ws[buf];
#pragma unroll
            for (int ks = 0; ks < 4; ks++) {
                uint32_t af[4][4];
#pragma unroll
                for (int mt = 0; mt < 4; mt++) {
                    const float* p = as + (wm * 64 + mt * 16 + r) * A_STR + ks * 8 + cl;
                    af[mt][0] = f2tf(p[0]);
                    af[mt][1] = f2tf(p[8 * A_STR]);
                    af[mt][2] = f2tf(p[4]);
                    af[mt][3] = f2tf(p[8 * A_STR + 4]);
                }
                uint32_t bf[4][2];
#pragma unroll
                for (int nt = 0; nt < 4; nt++) {
                    const float* p = ws + (ks * 8 + cl) * W_STR + wn * 32 + nt * 8 + r;
                    bf[nt][0] = f2tf(p[0]);
                    bf[nt][1] = f2tf(p[4 * W_STR]);
                }
#pragma unroll
                for (int mt = 0; mt < 4; mt++)
#pragma unroll
                    for (int nt = 0; nt < 4; nt++)
                        mma_tf32(acc[mt][nt], af[mt], bf[nt]);
            }
            __syncthreads();
            buf ^= 1;
        }
    }
};

// QKV: blockIdx.z selects which projection
__global__ __launch_bounds__(256, 2) void qkv_gemm(
    const float* __restrict__ x,
    const float* __restrict__ Wq, const float* __restrict__ bq, float* __restrict__ qo,
    const float* __restrict__ Wk, const float* __restrict__ bk, float* __restrict__ ko,
    const float* __restrict__ Wv, const float* __restrict__ bv, float* __restrict__ vo)
{
    extern __shared__ float sm[];
    const float* W = (blockIdx.z == 0) ? Wq : (blockIdx.z == 1) ? Wk : Wv;
    const float* bias = (blockIdx.z == 0) ? bq : (blockIdx.z == 1) ? bk : bv;
    float* C = (blockIdx.z == 0) ? qo : (blockIdx.z == 1) ? ko : vo;

    GemmCore g;
    g.A = x; g.W = W; g.N = DIMM; g.K = DIMM;
    g.bm = blockIdx.y * 128; g.bn = blockIdx.x * 128; g.smem = sm;
    g.run(threadIdx.x);

    const int lane = threadIdx.x & 31, warp = threadIdx.x >> 5;
    const int wm = warp >> 2, wn = warp & 3;
    const int r = lane >> 2, cl = lane & 3;
#pragma unroll
    for (int mt = 0; mt < 4; mt++) {
        const int row0 = g.bm + wm * 64 + mt * 16 + r;
#pragma unroll
        for (int nt = 0; nt < 4; nt++) {
            const int col = g.bn + wn * 32 + nt * 8 + 2 * cl;
            const float b0 = bias[col], b1 = bias[col + 1];
            *(float2*)(C + (size_t)row0 * DIMM + col) =
                make_float2(g.acc[mt][nt][0] + b0, g.acc[mt][nt][1] + b1);
            *(float2*)(C + (size_t)(row0 + 8) * DIMM + col) =
                make_float2(g.acc[mt][nt][2] + b0, g.acc[mt][nt][3] + b1);
        }
    }
}

// O projection with residual
__global__ __launch_bounds__(256, 2) void o_gemm(
    const float* __restrict__ A, const float* __restrict__ W,
    const float* __restrict__ bias, const float* __restrict__ resid,
    float* __restrict__ C)
{
    extern __shared__ float sm[];
    GemmCore g;
    g.A = A; g.W = W; g.N = DIMM; g.K = DIMM;
    g.bm = blockIdx.y * 128; g.bn = blockIdx.x * 128; g.smem = sm;
    g.run(threadIdx.x);

    const int lane = threadIdx.x & 31, warp = threadIdx.x >> 5;
    const int wm = warp >> 2, wn = warp & 3;
    const int r = lane >> 2, cl = lane & 3;
#pragma unroll
    for (int mt = 0; mt < 4; mt++) {
        const int row0 = g.bm + wm * 64 + mt * 16 + r;
#pragma unroll
        for (int nt = 0; nt < 4; nt++) {
            const int col = g.bn + wn * 32 + nt * 8 + 2 * cl;
            const float b0 = bias[col], b1 = bias[col + 1];
            float v00 = g.acc[mt][nt][0] + b0 + resid[(size_t)row0 * DIMM + col];
            float v01 = g.acc[mt][nt][1] + b1 + resid[(size_t)row0 * DIMM + col + 1];
            float v10 = g.acc[mt][nt][2] + b0 + resid[(size_t)(row0 + 8) * DIMM + col];
            float v11 = g.acc[mt][nt][3] + b1 + resid[(size_t)(row0 + 8) * DIMM + col + 1];
            *(float2*)(C + (size_t)row0 * DIMM + col)       = make_float2(v00, v01);
            *(float2*)(C + (size_t)(row0 + 8) * DIMM + col) = make_float2(v10, v11);
        }
    }
}

// ---------------------------------------------------------------------------
// scores_kernel: S_raw[b,h,s,t] = (Q.K^T)/8. 128x128 tile, K=64 single shot.
// grid (8 t-tiles, 8 s-tiles, 64 bh)
// ---------------------------------------------------------------------------
#define SC_STR 68
#define SC_SMEM (2 * 128 * SC_STR * 4)   // 69632 B

__global__ __launch_bounds__(256, 2) void scores_kernel(
    const float* __restrict__ q, const float* __restrict__ k,
    float* __restrict__ sraw)
{
    extern __shared__ float sm[];
    float* sQ = sm;                 // [128][SC_STR]
    float* sK = sm + 128 * SC_STR;  // [128][SC_STR]

    const int tid = threadIdx.x;
    const int lane = tid & 31, warp = tid >> 5;
    const int wm = warp >> 2, wn = warp & 3;
    const int r = lane >> 2, cl = lane & 3;

    const int bh = blockIdx.z;
    const int b = bh >> 4, h = bh & 15;
    const int s0 = blockIdx.y * 128;
    const int t0 = blockIdx.x * 128;

    const float* qb = q + ((size_t)b * SS + s0) * DIMM + h * SZ;
    const float* kb = k + ((size_t)b * SS + t0) * DIMM + h * SZ;

    // stage Q (prescaled) and K
    for (int idx = tid; idx < 128 * 16; idx += 256) {
        const int rr = idx >> 4, c4 = (idx & 15) * 4;
        float4 qv = *(const float4*)(qb + (size_t)rr * DIMM + c4);
        qv.x *= 0.125f; qv.y *= 0.125f; qv.z *= 0.125f; qv.w *= 0.125f;
        *(float4*)&sQ[rr * SC_STR + c4] = qv;
        *(float4*)&sK[rr * SC_STR + c4] = *(const float4*)(kb + (size_t)rr * DIMM + c4);
    }
    __syncthreads();

    float acc[4][4][4];
#pragma unroll
    for (int mt = 0; mt < 4; mt++)
#pragma unroll
        for (int nt = 0; nt < 4; nt++)
#pragma unroll
            for (int i = 0; i < 4; i++) acc[mt][nt][i] = 0.f;

#pragma unroll
    for (int ks = 0; ks < 8; ks++) {
        uint32_t af[4][4];
#pragma unroll
        for (int mt = 0; mt < 4; mt++) {
            const float* p = sQ + (wm * 64 + mt * 16 + r) * SC_STR + ks * 8 + cl;
            af[mt][0] = f2tf(p[0]);
            af[mt][1] = f2tf(p[8 * SC_STR]);
            af[mt][2] = f2tf(p[4]);
            af[mt][3] = f2tf(p[8 * SC_STR + 4]);
        }
        uint32_t bf[4][2];
#pragma unroll
        for (int nt = 0; nt < 4; nt++) {
            const float* p = sK + (wn * 32 + nt * 8 + r) * SC_STR + ks * 8 + cl;
            bf[nt][0] = f2tf(p[0]);
            bf[nt][1] = f2tf(p[4]);
        }
#pragma unroll
        for (int mt = 0; mt < 4; mt++)
#pragma unroll
            for (int nt = 0; nt < 4; nt++)
                mma_tf32(acc[mt][nt], af[mt], bf[nt]);
    }

    float* ob = sraw + (((size_t)bh) * SS + s0) * SS + t0;
#pragma unroll
    for (int mt = 0; mt < 4; mt++) {
        const int row0 = wm * 64 + mt * 16 + r;
#pragma unroll
        for (int nt = 0; nt < 4; nt++) {
            const int col = wn * 32 + nt * 8 + 2 * cl;
            *(float2*)(ob + (size_t)row0 * SS + col) =
                make_float2(acc[mt][nt][0], acc[mt][nt][1]);
            *(float2*)(ob + (size_t)(row0 + 8) * SS + col) =
                make_float2(acc[mt][nt][2], acc[mt][nt][3]);
        }
    }
}

// ---------------------------------------------------------------------------
// softmax_kernel: in-place. p = softmax(s_raw + rel + mask*NINF) per row.
// grid = BB*HH*SS blocks (row index), 256 threads, 4 floats per thread.
// ---------------------------------------------------------------------------
__global__ __launch_bounds__(256) void softmax_kernel(
    float* __restrict__ attn, const float* __restrict__ rel,
    const int* __restrict__ mask)
{
    __shared__ float sred[8];
    const int row = blockIdx.x;          // (b*16 + h)*1024 + s
    const int tid = threadIdx.x;
    const int b = row >> 14;             // /16384
    const int hs = row & 16383;          // h*1024 + s

    float4* rowp = (float4*)(attn + (size_t)row * SS);
    const float4 rl = ((const float4*)(rel + (size_t)hs * SS))[tid];
    const int4 mk = ((const int4*)(mask + b * SS))[tid];

    float4 sv = rowp[tid];
    sv.x += rl.x + (float)mk.x * NINF;
    sv.y += rl.y + (float)mk.y * NINF;
    sv.z += rl.z + (float)mk.z * NINF;
    sv.w += rl.w + (float)mk.w * NINF;

    // max
    float mx = fmaxf(fmaxf(sv.x, sv.y), fmaxf(sv.z, sv.w));
#pragma unroll
    for (int o = 16; o >= 1; o >>= 1) mx = fmaxf(mx, __shfl_xor_sync(~0u, mx, o));
    if ((tid & 31) == 0) sred[tid >> 5] = mx;
    __syncthreads();
    float rowmax = sred[0];
#pragma unroll
    for (int i = 1; i < 8; i++) rowmax = fmaxf(rowmax, sred[i]);

    float4 ev;
    ev.x = __expf(sv.x - rowmax);
    ev.y = __expf(sv.y - rowmax);
    ev.z = __expf(sv.z - rowmax);
    ev.w = __expf(sv.w - rowmax);
    float s = ev.x + ev.y + ev.z + ev.w;
#pragma unroll
    for (int o = 16; o >= 1; o >>= 1) s += __shfl_xor_sync(~0u, s, o);
    __syncthreads();
    if ((tid & 31) == 0) sred[tid >> 5] = s;
    __syncthreads();
    float tot = 0.f;
#pragma unroll
    for (int i = 0; i < 8; i++) tot += sred[i];
    const float inv = 1.f / tot;

    ev.x *= inv; ev.y *= inv; ev.z *= inv; ev.w *= inv;
    rowp[tid] = ev;
}

// ---------------------------------------------------------------------------
// pv_kernel: ctx[b,s,h*64+d] = sum_t P[b,h,s,t] V[b,t,h*64+d]
// Tile 128(M) x 64(N), K chunks of 64 double-buffered. grid (8 m-tiles, 64 bh)
// ---------------------------------------------------------------------------
#define P_STR 68
#define V_STR 72
#define PV_CHUNK_FLOATS (128 * P_STR + 64 * V_STR)
#define PV_SMEM (2 * PV_CHUNK_FLOATS * 4)   // 106496 B

__global__ __launch_bounds__(256, 1) void pv_kernel(
    const float* __restrict__ attn, const float* __restrict__ v,
    float* __restrict__ ctx)
{
    extern __shared__ float sm[];
    float* sP[2] = { sm, sm + PV_CHUNK_FLOATS };
    float* sV[2] = { sm + 128 * P_STR, sm + PV_CHUNK_FLOATS + 128 * P_STR };

    const int tid = threadIdx.x;
    const int lane = tid & 31, warp = tid >> 5;
    const int wm = warp >> 2, wn = warp & 3;
    const int r = lane >> 2, cl = lane & 3;

    const int bh = blockIdx.y;
    const int b = bh >> 4, h = bh & 15;
    const int s0 = blockIdx.x * 128;

    const float* pb = attn + (((size_t)bh) * SS + s0) * SS;
    const float* vb = v + (size_t)b * SS * DIMM + h * SZ;

    auto load_stage = [&](int buf, int t0) {
#pragma unroll
        for (int j = 0; j < 8; j++) {   // P: 128x16 float4
            const int idx = tid + j * 256;
            const int pr = idx >> 4, c4 = (idx & 15) * 4;
            cp16((uint32_t)__cvta_generic_to_shared(sP[buf] + pr * P_STR + c4),
                 pb + (size_t)pr * SS + t0 + c4);
        }
#pragma unroll
        for (int j = 0; j < 4; j++) {   // V: 64x16 float4
            const int idx = tid + j * 256;
            const int vr = idx >> 4, c4 = (idx & 15) * 4;
            cp16((uint32_t)__cvta_generic_to_shared(sV[buf] + vr * V_STR + c4),
                 vb + (size_t)(t0 + vr) * DIMM + c4);
        }
    };

    float acc[4][2][4];
#pragma unroll
    for (int mt = 0; mt < 4; mt++)
#pragma unroll
        for (int nt = 0; nt < 2; nt++)
#pragma unroll
            for (int i = 0; i < 4; i++) acc[mt][nt][i] = 0.f;

    load_stage(0, 0);
    CP_COMMIT();

    int buf = 0;
    for (int t = 0; t < 16; t++) {
        if (t + 1 < 16) { load_stage(buf ^ 1, (t + 1) * 64); CP_COMMIT(); CP_WAIT1(); }
        else            { CP_WAIT0(); }
        __syncthreads();
        const float* ps = sP[buf];
        const float* vs = sV[buf];
#pragma unroll
        for (int ks = 0; ks < 8; ks++) {
            uint32_t af[4][4];
#pragma unroll
            for (int mt = 0; mt < 4; mt++) {
                const float* p = ps + (wm * 64 + mt * 16 + r) * P_STR + ks * 8 + cl;
                af[mt][0] = f2tf(p[0]);
                af[mt][1] = f2tf(p[8 * P_STR]);
                af[mt][2] = f2tf(p[4]);
                af[mt][3] = f2tf(p[8 * P_STR + 4]);
            }
            uint32_t bf[2][2];
#pragma unroll
            for (int nt = 0; nt < 2; nt++) {
                const float* p = vs + (ks * 8 + cl) * V_STR + wn * 16 + nt * 8 + r;
                bf[nt][0] = f2tf(p[0]);
                bf[nt][1] = f2tf(p[4 * V_STR]);
            }
#pragma unroll
            for (int mt = 0; mt < 4; mt++)
#pragma unroll
                for (int nt = 0; nt < 2; nt++)
                    mma_tf32(acc[mt][nt], af[mt], bf[nt]);
        }
        __syncthreads();
        buf ^= 1;
    }

#pragma unroll
    for (int mt = 0; mt < 4; mt++) {
        const int row0 = s0 + wm * 64 + mt * 16 + r;
#pragma unroll
        for (int nt = 0; nt < 2; nt++) {
            const int col = h * SZ + wn * 16 + nt * 8 + 2 * cl;
            *(float2*)(ctx + ((size_t)b * SS + row0) * DIMM + col) =
                make_float2(acc[mt][nt][0], acc[mt][nt][1]);
            *(float2*)(ctx + ((size_t)b * SS + row0 + 8) * DIMM + col) =
                make_float2(acc[mt][nt][2], acc[mt][nt][3]);
        }
    }
}

// ---------------------------------------------------------------------------
// LayerNorm
// ---------------------------------------------------------------------------
__global__ __launch_bounds__(256) void ln_kernel(
    const float* __restrict__ res, const float* __restrict__ gamma,
    const float* __restrict__ beta, float* __restrict__ out)
{
    __shared__ float sred[2][8];
    const int row = blockIdx.x;
    const int tid = threadIdx.x;
    const float4 vv = ((const float4*)(res + (size_t)row * DIMM))[tid];
    float s  = vv.x + vv.y + vv.z + vv.w;
    float ss = vv.x * vv.x + vv.y * vv.y + vv.z * vv.z + vv.w * vv.w;
#pragma unroll
    for (int o = 16; o >= 1; o >>= 1) {
        s  += __shfl_xor_sync(~0u, s, o);
        ss += __shfl_xor_sync(~0u, ss, o);
    }
    if ((tid & 31) == 0) { sred[0][tid >> 5] = s; sred[1][tid >> 5] = ss; }
    __syncthreads();
    float ts = 0.f, tss = 0.f;
#pragma unroll
    for (int i = 0; i < 8; i++) { ts += sred[0][i]; tss += sred[1][i]; }
    const float mu   = ts * (1.f / DIMM);
    const float var  = tss * (1.f / DIMM) - mu * mu;
    const float rstd = rsqrtf(var + 1e-6f);
    const float4 g  = ((const float4*)gamma)[tid];
    const float4 be = ((const float4*)beta)[tid];
    float4 o4;
    o4.x = (vv.x - mu) * rstd * g.x + be.x;
    o4.y = (vv.y - mu) * rstd * g.y + be.y;
    o4.z = (vv.z - mu) * rstd * g.z + be.z;
    o4.w = (vv.w - mu) * rstd * g.w + be.w;
    ((float4*)(out + (size_t)row * DIMM))[tid] = o4;
}

// ---------------------------------------------------------------------------
extern "C" void kernel_launch(void* const* d_in, const int* in_sizes, int n_in,
                              void* d_out, int out_size)
{
    const float* x     = (const float*)d_in[0];
    const int*   mask  = (const int*)d_in[1];
    const float* rel   = (const float*)d_in[2];
    const float* Wq    = (const float*)d_in[3];
    const float* bq    = (const float*)d_in[4];
    const float* Wk    = (const float*)d_in[5];
    const float* bk    = (const float*)d_in[6];
    const float* Wv    = (const float*)d_in[7];
    const float* bv    = (const float*)d_in[8];
    const float* Wo    = (const float*)d_in[9];
    const float* bo    = (const float*)d_in[10];
    const float* gamma = (const float*)d_in[11];
    const float* beta  = (const float*)d_in[12];
    float* out = (float*)d_out;

    float *q, *k, *v, *ctx, *res, *attn_scr;
    cudaGetSymbolAddress((void**)&q,        g_q);
    cudaGetSymbolAddress((void**)&k,        g_k);
    cudaGetSymbolAddress((void**)&v,        g_v);
    cudaGetSymbolAddress((void**)&ctx,      g_ctx);
    cudaGetSymbolAddress((void**)&res,      g_res);
    cudaGetSymbolAddress((void**)&attn_scr, g_attn_scratch);

    const size_t OUT_E  = (size_t)BB * SS * DIMM;
    const size_t ATTN_E = (size_t)BB * HH * SS * SS;
    float* attn = ((size_t)out_size >= OUT_E + ATTN_E) ? (out + OUT_E)
                                                       : attn_scr;

    cudaFuncSetAttribute(qkv_gemm,
                         cudaFuncAttributeMaxDynamicSharedMemorySize, GEMM_SMEM);
    cudaFuncSetAttribute(o_gemm,
                         cudaFuncAttributeMaxDynamicSharedMemorySize, GEMM_SMEM);
    cudaFuncSetAttribute(scores_kernel,
                         cudaFuncAttributeMaxDynamicSharedMemorySize, SC_SMEM);
    cudaFuncSetAttribute(pv_kernel,
                         cudaFuncAttributeMaxDynamicSharedMemorySize, PV_SMEM);

    const int M = BB * SS;  // 4096

    qkv_gemm<<<dim3(DIMM / 128, M / 128, 3), 256, GEMM_SMEM>>>(
        x, Wq, bq, q, Wk, bk, k, Wv, bv, v);

    scores_kernel<<<dim3(8, 8, BB * HH), 256, SC_SMEM>>>(q, k, attn);

    softmax_kernel<<<BB * HH * SS, 256>>>(attn, rel, mask);

    pv_kernel<<<dim3(8, BB * HH), 256, PV_SMEM>>>(attn, v, ctx);

    o_gemm<<<dim3(DIMM / 128, M / 128), 256, GEMM_SMEM>>>(ctx, Wo, bo, x, res);

    ln_kernel<<<M, 256>>>(res, gamma, beta, out);
}